// round 8
// baseline (speedup 1.0000x reference)
#include <cuda_runtime.h>
#include <cuda_bf16.h>
#include <cstdint>
#include <cstddef>

#define DD 128
#define VMAX 100000

// ---------------------------------------------------------------------------
// Global scratch (no allocs allowed)
// ---------------------------------------------------------------------------
__device__ float g_Y[2u * VMAX * DD];                    // Y_in | Y_out, fp32
__device__ float g_stats[2 * DD];                        // BN sum / sumsq
// W images: 12 chunks (in k0..3 | out k0..3 | loop k0..3), each [128 n][32 k] bf16
__device__ __align__(16) unsigned char g_Bhi[12 * 8192];
__device__ __align__(16) unsigned char g_Blo[12 * 8192];

// ---------------------------------------------------------------------------
// PTX helpers (generic-target safe: ldmatrix + mma.sync + cp.async)
// ---------------------------------------------------------------------------
__device__ __forceinline__ uint32_t smem_u32(const void* p) {
    uint32_t a;
    asm("{ .reg .u64 t; cvta.to.shared.u64 t, %1; cvt.u32.u64 %0, t; }" : "=r"(a) : "l"(p));
    return a;
}

#define LDSM4(r, addr)                                                          \
    asm volatile("ldmatrix.sync.aligned.m8n8.x4.shared.b16 {%0,%1,%2,%3}, [%4];" \
        : "=r"((r)[0]), "=r"((r)[1]), "=r"((r)[2]), "=r"((r)[3]) : "r"(addr))

#define MMA16816(d, a, b0, b1)                                                  \
    asm volatile("mma.sync.aligned.m16n8k16.row.col.f32.bf16.bf16.f32 "         \
        "{%0,%1,%2,%3}, {%4,%5,%6,%7}, {%8,%9}, {%0,%1,%2,%3};"                 \
        : "+f"((d)[0]), "+f"((d)[1]), "+f"((d)[2]), "+f"((d)[3])                \
        : "r"((a)[0]), "r"((a)[1]), "r"((a)[2]), "r"((a)[3]), "r"(b0), "r"(b1))

#define CP_ASYNC16(saddr, gptr)                                                 \
    asm volatile("cp.async.cg.shared.global [%0], [%1], 16;"                    \
        :: "r"(saddr), "l"(gptr) : "memory")
#define CP_ASYNC16Z(saddr, gptr, sz)                                            \
    asm volatile("cp.async.cg.shared.global [%0], [%1], 16, %2;"                \
        :: "r"(saddr), "l"(gptr), "r"(sz) : "memory")
#define CP_COMMIT()  asm volatile("cp.async.commit_group;" ::: "memory")
#define CP_WAIT0()   asm volatile("cp.async.wait_group 0;" ::: "memory")

// Truncation split: hi = upper-16 bits of fp32 (bf16-trunc), lo = bf16-trunc(z - hi).
__device__ __forceinline__ void split4(const float4 z, uint2& hi, uint2& lo) {
    uint32_t ux = __float_as_uint(z.x), uy = __float_as_uint(z.y);
    uint32_t uz = __float_as_uint(z.z), uw = __float_as_uint(z.w);
    float lx = z.x - __uint_as_float(ux & 0xFFFF0000u);
    float ly = z.y - __uint_as_float(uy & 0xFFFF0000u);
    float lz = z.z - __uint_as_float(uz & 0xFFFF0000u);
    float lw = z.w - __uint_as_float(uw & 0xFFFF0000u);
    hi.x = __byte_perm(ux, uy, 0x7632);
    hi.y = __byte_perm(uz, uw, 0x7632);
    lo.x = __byte_perm(__float_as_uint(lx), __float_as_uint(ly), 0x7632);
    lo.y = __byte_perm(__float_as_uint(lz), __float_as_uint(lw), 0x7632);
}

// ---------------------------------------------------------------------------
// Kernel 0: pre-split W into bf16 hi/lo chunk images, [n][k] rows of 32 bf16.
// ---------------------------------------------------------------------------
__global__ void prep_w(const float* __restrict__ in_w, const float* __restrict__ out_w,
                       const float* __restrict__ loop_w) {
    int c = blockIdx.x;
    const float* W = (c < 4) ? in_w : (c < 8 ? out_w : loop_w);
    int k0 = (c & 3) * 32;
    unsigned short* bh = reinterpret_cast<unsigned short*>(g_Bhi + c * 8192);
    unsigned short* bl = reinterpret_cast<unsigned short*>(g_Blo + c * 8192);
    for (int i = threadIdx.x; i < 4096; i += blockDim.x) {
        int n = i >> 5, k = i & 31;
        float v = W[(size_t)(k0 + k) * DD + n];
        uint32_t u = __float_as_uint(v);
        float lf = v - __uint_as_float(u & 0xFFFF0000u);
        bh[n * 32 + k] = (unsigned short)(u >> 16);
        bl[n * 32 + k] = (unsigned short)(__float_as_uint(lf) >> 16);
    }
}

// ---------------------------------------------------------------------------
// Kernel 1: per-edge scatter for ONE direction.  yb[dst] += norm*(x[src]*rel[et])
// ---------------------------------------------------------------------------
__global__ void edge_kernel(const float* __restrict__ x,
                            const float* __restrict__ rel,
                            const float* __restrict__ enorm,
                            const int* __restrict__ src,
                            const int* __restrict__ dst,
                            const int* __restrict__ et,
                            int n_edges,
                            float* __restrict__ yb) {
    int e = (blockIdx.x * blockDim.x + threadIdx.x) >> 5;
    if (e >= n_edges) return;
    int lane = threadIdx.x & 31;

    int   s = __ldg(&src[e]);
    int   d = __ldg(&dst[e]);
    int   t = __ldg(&et[e]);
    float n = __ldg(&enorm[e]);

    float4 xv = __ldg(reinterpret_cast<const float4*>(x)   + (size_t)s * 32 + lane);
    float4 rv = __ldg(reinterpret_cast<const float4*>(rel) + (size_t)t * 32 + lane);

    float a = n * xv.x * rv.x;
    float b = n * xv.y * rv.y;
    float c = n * xv.z * rv.z;
    float w = n * xv.w * rv.w;

    float* yp = yb + (size_t)d * DD + lane * 4;
    asm volatile("red.global.add.v4.f32 [%0], {%1,%2,%3,%4};"
                 :: "l"(yp), "f"(a), "f"(b), "f"(c), "f"(w) : "memory");
}

// ---------------------------------------------------------------------------
// Kernel 2: mma.sync bf16 hi/lo GEMM, cp.async smem pipeline, fused BN stats.
// smem layout (dynamic, 98304 B total):
//   [0      : 10240)  Ah   (128 rows x 80B)     single buffer
//   [10240  : 20480)  Al
//   [20480  : 57344)  Araw stages 0/1 (128 rows x 144B = 18432 each)
//   [57344  : 98304)  B stages 0/1: each {Bh 10240, Bl 10240}
// ---------------------------------------------------------------------------
#define ROWB 80
#define ARAWB 144
#define OAH  0
#define OAL  10240
#define ARAW(s) (20480 + (s) * 18432)
#define OBH(s)  (57344 + (s) * 20480)
#define OBL(s)  (57344 + (s) * 20480 + 10240)
#define SMEM_GEMM 98304

__global__ void __launch_bounds__(256, 2) gemm_mma(
    const float* __restrict__ x,
    const float* __restrict__ loop_rel,
    const float* __restrict__ bias,
    float* __restrict__ hout,
    int V) {

    extern __shared__ __align__(16) unsigned char sm[];
    const uint32_t sb = smem_u32(sm);

    const int tid  = threadIdx.x;
    const int wid  = tid >> 5;
    const int lane = tid & 31;
    const int wm   = wid & 3;    // 4 warps over M (32 rows each)
    const int wn   = wid >> 2;   // 2 warps over N (64 cols each)
    const int m0   = blockIdx.x * 128;

    float acc[2][8][4];
#pragma unroll
    for (int i = 0; i < 2; i++)
#pragma unroll
        for (int j = 0; j < 8; j++)
#pragma unroll
            for (int k = 0; k < 4; k++) acc[i][j][k] = 0.f;

    // ---- async prefetch helpers (no registers held) ----
    auto cpA = [&](int c, int s) {
        const int k0 = (c & 3) * 32;
        const float* Ab = (c < 4) ? g_Y : (c < 8 ? g_Y + (size_t)V * DD : x);
#pragma unroll
        for (int j = 0; j < 4; j++) {
            int i = tid + j * 256;
            int r = i >> 3, g = i & 7;
            int v = m0 + r;
            uint32_t sz = (v < V) ? 16u : 0u;
            const float* src = Ab + (size_t)(v < V ? v : 0) * DD + k0 + g * 4;
            CP_ASYNC16Z(sb + ARAW(s) + r * ARAWB + g * 16, src, sz);
        }
    };
    auto cpB = [&](int c, int s) {
        const unsigned char* gh = g_Bhi + c * 8192;
        const unsigned char* gl = g_Blo + c * 8192;
#pragma unroll
        for (int j = 0; j < 2; j++) {
            int i = tid + j * 256;          // 0..511 16B-chunks
            int r = i >> 2, g = i & 3;
            CP_ASYNC16(sb + OBH(s) + r * ROWB + g * 16, gh + r * 64 + g * 16);
            CP_ASYNC16(sb + OBL(s) + r * ROWB + g * 16, gl + r * 64 + g * 16);
        }
    };
    // ---- split phase: raw fp32 smem -> bf16 hi/lo smem ----
    auto splitA = [&](int c, int s) {
        const bool is_loop = (c >= 8);
        const int k0 = (c & 3) * 32;
#pragma unroll
        for (int j = 0; j < 4; j++) {
            int i = tid + j * 256;
            int r = i >> 3, g = i & 7;
            float4 z = *reinterpret_cast<const float4*>(sm + ARAW(s) + r * ARAWB + g * 16);
            if (is_loop) {
                float4 lr = __ldg(reinterpret_cast<const float4*>(loop_rel + k0 + g * 4));
                z.x *= lr.x; z.y *= lr.y; z.z *= lr.z; z.w *= lr.w;
            }
            uint2 hi, lo;
            split4(z, hi, lo);
            *reinterpret_cast<uint2*>(sm + OAH + r * ROWB + g * 8) = hi;
            *reinterpret_cast<uint2*>(sm + OAL + r * ROWB + g * 8) = lo;
        }
    };

    // ---- prologue: stage 0 ----
    cpA(0, 0);
    cpB(0, 0);
    CP_COMMIT();
    CP_WAIT0();
    __syncthreads();

    for (int c = 0; c < 12; c++) {
        const int s = c & 1;
        if (c < 11) {               // prefetch next chunk under this chunk's work
            cpA(c + 1, s ^ 1);
            cpB(c + 1, s ^ 1);
            CP_COMMIT();
        }

        splitA(c, s);
        __syncthreads();

        // ---- mma over 2 K16 steps ----
#pragma unroll
        for (int k16 = 0; k16 < 2; k16++) {
            const uint32_t kb = k16 * 32 + ((lane >> 4) << 4);
            const uint32_t arow = (uint32_t)(wm * 32 + (lane & 15)) * ROWB + kb;
            const uint32_t brow = (uint32_t)(wn * 64 + (lane & 15)) * ROWB + kb;

            uint32_t ah[2][4], al[2][4], bh[4][4], bl[4][4];
#pragma unroll
            for (int mt = 0; mt < 2; mt++) LDSM4(ah[mt], sb + OAH + arow + mt * 16 * ROWB);
#pragma unroll
            for (int nb = 0; nb < 4; nb++) LDSM4(bh[nb], sb + OBH(s) + brow + nb * 16 * ROWB);
#pragma unroll
            for (int mt = 0; mt < 2; mt++)
#pragma unroll
                for (int nb = 0; nb < 4; nb++) {
                    MMA16816(acc[mt][nb * 2 + 0], ah[mt], bh[nb][0], bh[nb][2]);
                    MMA16816(acc[mt][nb * 2 + 1], ah[mt], bh[nb][1], bh[nb][3]);
                }
#pragma unroll
            for (int nb = 0; nb < 4; nb++) LDSM4(bl[nb], sb + OBL(s) + brow + nb * 16 * ROWB);
#pragma unroll
            for (int mt = 0; mt < 2; mt++)
#pragma unroll
                for (int nb = 0; nb < 4; nb++) {
                    MMA16816(acc[mt][nb * 2 + 0], ah[mt], bl[nb][0], bl[nb][2]);
                    MMA16816(acc[mt][nb * 2 + 1], ah[mt], bl[nb][1], bl[nb][3]);
                }
#pragma unroll
            for (int mt = 0; mt < 2; mt++) LDSM4(al[mt], sb + OAL + arow + mt * 16 * ROWB);
#pragma unroll
            for (int mt = 0; mt < 2; mt++)
#pragma unroll
                for (int nb = 0; nb < 4; nb++) {
                    MMA16816(acc[mt][nb * 2 + 0], al[mt], bh[nb][0], bh[nb][2]);
                    MMA16816(acc[mt][nb * 2 + 1], al[mt], bh[nb][1], bh[nb][3]);
                }
        }

        if (c < 11) CP_WAIT0();     // next raw/B stage landed
        __syncthreads();            // Ah/Al free; stage ready
    }

    // ---- epilogue: /3 + bias, store h, accumulate BN stats ----
    const float third = 1.f / 3.f;
    float ssum[16], ssq[16];
#pragma unroll
    for (int i = 0; i < 16; i++) { ssum[i] = 0.f; ssq[i] = 0.f; }

#pragma unroll
    for (int mt = 0; mt < 2; mt++) {
        int rowa = m0 + wm * 32 + mt * 16 + (lane >> 2);
        int rowb = rowa + 8;
#pragma unroll
        for (int nt = 0; nt < 8; nt++) {
            int col = wn * 64 + nt * 8 + (lane & 3) * 2;
            float2 bv = *reinterpret_cast<const float2*>(bias + col);
            float h0 = acc[mt][nt][0] * third + bv.x;
            float h1 = acc[mt][nt][1] * third + bv.y;
            float h2 = acc[mt][nt][2] * third + bv.x;
            float h3 = acc[mt][nt][3] * third + bv.y;
            if (rowa < V) {
                *reinterpret_cast<float2*>(hout + (size_t)rowa * DD + col) =
                    make_float2(h0, h1);
                ssum[nt * 2 + 0] += h0; ssq[nt * 2 + 0] += h0 * h0;
                ssum[nt * 2 + 1] += h1; ssq[nt * 2 + 1] += h1 * h1;
            }
            if (rowb < V) {
                *reinterpret_cast<float2*>(hout + (size_t)rowb * DD + col) =
                    make_float2(h2, h3);
                ssum[nt * 2 + 0] += h2; ssq[nt * 2 + 0] += h2 * h2;
                ssum[nt * 2 + 1] += h3; ssq[nt * 2 + 1] += h3 * h3;
            }
        }
    }
#pragma unroll
    for (int i = 0; i < 16; i++) {
#pragma unroll
        for (int off = 4; off <= 16; off <<= 1) {
            ssum[i] += __shfl_xor_sync(0xFFFFFFFFu, ssum[i], off);
            ssq[i]  += __shfl_xor_sync(0xFFFFFFFFu, ssq[i],  off);
        }
    }
    __syncthreads();
    float* Ssum = reinterpret_cast<float*>(sm);          // [8][128]
    float* Ssq  = reinterpret_cast<float*>(sm + 4096);   // [8][128]
#pragma unroll
    for (int j = 0; j < 4; j++) { Ssum[tid + j * 256] = 0.f; Ssq[tid + j * 256] = 0.f; }
    __syncthreads();
    if (lane < 4) {
#pragma unroll
        for (int nt = 0; nt < 8; nt++) {
            int col = wn * 64 + nt * 8 + lane * 2;
            Ssum[wid * 128 + col]     = ssum[nt * 2 + 0];
            Ssum[wid * 128 + col + 1] = ssum[nt * 2 + 1];
            Ssq [wid * 128 + col]     = ssq[nt * 2 + 0];
            Ssq [wid * 128 + col + 1] = ssq[nt * 2 + 1];
        }
    }
    __syncthreads();
    if (tid < 128) {
        float a = 0.f, b = 0.f;
#pragma unroll
        for (int w = 0; w < 8; w++) { a += Ssum[w * 128 + tid]; b += Ssq[w * 128 + tid]; }
        atomicAdd(&g_stats[tid],       a);
        atomicAdd(&g_stats[128 + tid], b);
    }
}

// ---------------------------------------------------------------------------
// Kernel 3: BatchNorm + ReLU, in place on h
// ---------------------------------------------------------------------------
__global__ void bn_kernel(float* __restrict__ h, int V) {
    __shared__ float ms[128];
    __shared__ float rs[128];
    if (threadIdx.x < 128) {
        float invn = 1.f / (float)V;
        float s  = g_stats[threadIdx.x];
        float sq = g_stats[128 + threadIdx.x];
        float m  = s * invn;
        float var = sq * invn - m * m;
        ms[threadIdx.x] = m;
        rs[threadIdx.x] = rsqrtf(var + 1e-5f);
    }
    __syncthreads();
    size_t total = (size_t)V * 32;
    float4* h4 = reinterpret_cast<float4*>(h);
    for (size_t i = (size_t)blockIdx.x * blockDim.x + threadIdx.x; i < total;
         i += (size_t)gridDim.x * blockDim.x) {
        int c4 = (int)(i & 31) * 4;
        float4 hv = h4[i];
        hv.x = fmaxf((hv.x - ms[c4 + 0]) * rs[c4 + 0], 0.f);
        hv.y = fmaxf((hv.y - ms[c4 + 1]) * rs[c4 + 1], 0.f);
        hv.z = fmaxf((hv.z - ms[c4 + 2]) * rs[c4 + 2], 0.f);
        hv.w = fmaxf((hv.w - ms[c4 + 3]) * rs[c4 + 3], 0.f);
        h4[i] = hv;
    }
}

// ---------------------------------------------------------------------------
// Kernel 4: rel_repr @ w_rel, 4 rel rows per block
// ---------------------------------------------------------------------------
__global__ void relw_kernel(const float* __restrict__ rel,
                            const float* __restrict__ w_rel,
                            float* __restrict__ out, int R) {
    __shared__ float rr[4][128];
    int r0 = blockIdx.x * 4;
    int c = threadIdx.x;
#pragma unroll
    for (int j = 0; j < 4; j++)
        rr[j][c] = (r0 + j < R) ? rel[(size_t)(r0 + j) * DD + c] : 0.f;
    __syncthreads();
    float a0 = 0.f, a1 = 0.f, a2 = 0.f, a3 = 0.f;
#pragma unroll 4
    for (int k = 0; k < 128; k++) {
        float w = __ldg(&w_rel[(size_t)k * DD + c]);
        a0 += rr[0][k] * w;
        a1 += rr[1][k] * w;
        a2 += rr[2][k] * w;
        a3 += rr[3][k] * w;
    }
    if (r0 + 0 < R) out[(size_t)(r0 + 0) * DD + c] = a0;
    if (r0 + 1 < R) out[(size_t)(r0 + 1) * DD + c] = a1;
    if (r0 + 2 < R) out[(size_t)(r0 + 2) * DD + c] = a2;
    if (r0 + 3 < R) out[(size_t)(r0 + 3) * DD + c] = a3;
}

// ---------------------------------------------------------------------------
extern "C" void kernel_launch(void* const* d_in, const int* in_sizes, int n_in,
                              void* d_out, int out_size) {
    const float* x        = (const float*)d_in[0];
    const float* rel      = (const float*)d_in[1];
    const float* enorm    = (const float*)d_in[2];
    const float* in_w     = (const float*)d_in[3];
    const float* out_w    = (const float*)d_in[4];
    const float* loop_w   = (const float*)d_in[5];
    const float* w_rel    = (const float*)d_in[6];
    const float* loop_rel = (const float*)d_in[7];
    const float* bias     = (const float*)d_in[8];
    const int*   src      = (const int*)d_in[9];
    const int*   dst      = (const int*)d_in[10];
    const int*   et       = (const int*)d_in[11];

    int V = in_sizes[0] / DD;
    int R = in_sizes[1] / DD;
    int E = in_sizes[2];
    int half = E / 2;

    float* h    = (float*)d_out;
    float* out2 = h + (size_t)V * DD;

    void* yptr = nullptr; void* sptr = nullptr;
    cudaGetSymbolAddress(&yptr, g_Y);
    cudaGetSymbolAddress(&sptr, g_stats);
    float* Yin  = (float*)yptr;
    float* Yout = Yin + (size_t)V * DD;
    cudaMemsetAsync(yptr, 0, (size_t)2 * V * DD * sizeof(float), 0);
    cudaMemsetAsync(sptr, 0, 2 * DD * sizeof(float), 0);

    cudaFuncSetAttribute(gemm_mma, cudaFuncAttributeMaxDynamicSharedMemorySize,
                         SMEM_GEMM);

    prep_w<<<12, 256>>>(in_w, out_w, loop_w);
    // two passes: per-launch working set (x + half of Y) fits in L2
    edge_kernel<<<(half + 7) / 8, 256>>>(x, rel, enorm, src, dst, et, half, Yin);
    edge_kernel<<<(E - half + 7) / 8, 256>>>(x, rel, enorm + half, src + half,
                                             dst + half, et + half, E - half, Yout);
    gemm_mma<<<(V + 127) / 128, 256, SMEM_GEMM>>>(x, loop_rel, bias, h, V);
    bn_kernel<<<1024, 256>>>(h, V);
    relw_kernel<<<(R + 3) / 4, 128>>>(rel, w_rel, out2, R);
}

// round 9
// speedup vs baseline: 1.0511x; 1.0511x over previous
#include <cuda_runtime.h>
#include <cuda_bf16.h>
#include <cstdint>
#include <cstddef>

#define DD 128
#define VMAX 100000

// ---------------------------------------------------------------------------
// Global scratch (no allocs allowed)
// ---------------------------------------------------------------------------
__device__ float g_Y[2u * VMAX * DD];                    // Y_in | Y_out, fp32
__device__ float g_stats[2 * DD];                        // BN sum / sumsq
// W images: 12 chunks (in k0..3 | out k0..3 | loop k0..3), each [128 n][32 k] bf16
__device__ __align__(16) unsigned char g_Bhi[12 * 8192];
__device__ __align__(16) unsigned char g_Blo[12 * 8192];

// ---------------------------------------------------------------------------
// PTX helpers (generic-target safe: ldmatrix + mma.sync + cp.async)
// ---------------------------------------------------------------------------
__device__ __forceinline__ uint32_t smem_u32(const void* p) {
    uint32_t a;
    asm("{ .reg .u64 t; cvta.to.shared.u64 t, %1; cvt.u32.u64 %0, t; }" : "=r"(a) : "l"(p));
    return a;
}

#define LDSM4(r, addr)                                                          \
    asm volatile("ldmatrix.sync.aligned.m8n8.x4.shared.b16 {%0,%1,%2,%3}, [%4];" \
        : "=r"((r)[0]), "=r"((r)[1]), "=r"((r)[2]), "=r"((r)[3]) : "r"(addr))

#define MMA16816(d, a, b0, b1)                                                  \
    asm volatile("mma.sync.aligned.m16n8k16.row.col.f32.bf16.bf16.f32 "         \
        "{%0,%1,%2,%3}, {%4,%5,%6,%7}, {%8,%9}, {%0,%1,%2,%3};"                 \
        : "+f"((d)[0]), "+f"((d)[1]), "+f"((d)[2]), "+f"((d)[3])                \
        : "r"((a)[0]), "r"((a)[1]), "r"((a)[2]), "r"((a)[3]), "r"(b0), "r"(b1))

#define CP_ASYNC16(saddr, gptr)                                                 \
    asm volatile("cp.async.cg.shared.global [%0], [%1], 16;"                    \
        :: "r"(saddr), "l"(gptr) : "memory")
#define CP_COMMIT()  asm volatile("cp.async.commit_group;" ::: "memory")
#define CP_WAIT0()   asm volatile("cp.async.wait_group 0;" ::: "memory")

// Truncation split: hi = upper-16 bits of fp32 (bf16-trunc), lo = bf16-trunc(z - hi).
__device__ __forceinline__ void split4(const float4 z, uint2& hi, uint2& lo) {
    uint32_t ux = __float_as_uint(z.x), uy = __float_as_uint(z.y);
    uint32_t uz = __float_as_uint(z.z), uw = __float_as_uint(z.w);
    float lx = z.x - __uint_as_float(ux & 0xFFFF0000u);
    float ly = z.y - __uint_as_float(uy & 0xFFFF0000u);
    float lz = z.z - __uint_as_float(uz & 0xFFFF0000u);
    float lw = z.w - __uint_as_float(uw & 0xFFFF0000u);
    hi.x = __byte_perm(ux, uy, 0x7632);
    hi.y = __byte_perm(uz, uw, 0x7632);
    lo.x = __byte_perm(__float_as_uint(lx), __float_as_uint(ly), 0x7632);
    lo.y = __byte_perm(__float_as_uint(lz), __float_as_uint(lw), 0x7632);
}

// ---------------------------------------------------------------------------
// Kernel 0: pre-split W into bf16 hi/lo chunk images, [n][k] rows of 32 bf16.
// ---------------------------------------------------------------------------
__global__ void prep_w(const float* __restrict__ in_w, const float* __restrict__ out_w,
                       const float* __restrict__ loop_w) {
    int c = blockIdx.x;
    const float* W = (c < 4) ? in_w : (c < 8 ? out_w : loop_w);
    int k0 = (c & 3) * 32;
    unsigned short* bh = reinterpret_cast<unsigned short*>(g_Bhi + c * 8192);
    unsigned short* bl = reinterpret_cast<unsigned short*>(g_Blo + c * 8192);
    for (int i = threadIdx.x; i < 4096; i += blockDim.x) {
        int n = i >> 5, k = i & 31;
        float v = W[(size_t)(k0 + k) * DD + n];
        uint32_t u = __float_as_uint(v);
        float lf = v - __uint_as_float(u & 0xFFFF0000u);
        bh[n * 32 + k] = (unsigned short)(u >> 16);
        bl[n * 32 + k] = (unsigned short)(__float_as_uint(lf) >> 16);
    }
}

// ---------------------------------------------------------------------------
// Kernel 1: per-edge scatter for ONE direction.  yb[dst] += norm*(x[src]*rel[et])
// ---------------------------------------------------------------------------
__global__ void edge_kernel(const float* __restrict__ x,
                            const float* __restrict__ rel,
                            const float* __restrict__ enorm,
                            const int* __restrict__ src,
                            const int* __restrict__ dst,
                            const int* __restrict__ et,
                            int n_edges,
                            float* __restrict__ yb) {
    int e = (blockIdx.x * blockDim.x + threadIdx.x) >> 5;
    if (e >= n_edges) return;
    int lane = threadIdx.x & 31;

    int   s = __ldg(&src[e]);
    int   d = __ldg(&dst[e]);
    int   t = __ldg(&et[e]);
    float n = __ldg(&enorm[e]);

    float4 xv = __ldg(reinterpret_cast<const float4*>(x)   + (size_t)s * 32 + lane);
    float4 rv = __ldg(reinterpret_cast<const float4*>(rel) + (size_t)t * 32 + lane);

    float a = n * xv.x * rv.x;
    float b = n * xv.y * rv.y;
    float c = n * xv.z * rv.z;
    float w = n * xv.w * rv.w;

    float* yp = yb + (size_t)d * DD + lane * 4;
    asm volatile("red.global.add.v4.f32 [%0], {%1,%2,%3,%4};"
                 :: "l"(yp), "f"(a), "f"(b), "f"(c), "f"(w) : "memory");
}

// ---------------------------------------------------------------------------
// Kernel 2: mma.sync bf16 hi/lo GEMM (single-buffered, reordered passes to
// keep peak live registers < 128), fused BN stats.
//   h[v,:] = ( [Yin | Yout | x*loop_rel][v,:384] @ [in_w; out_w; loop_w] )/3 + bias
// ---------------------------------------------------------------------------
#define ROWB 80   // bytes per smem row (64 B data + pad) — conflict-free ldmatrix

__global__ void __launch_bounds__(256, 2) gemm_mma(
    const float* __restrict__ x,
    const float* __restrict__ loop_rel,
    const float* __restrict__ bias,
    float* __restrict__ hout,
    int V) {

    __shared__ __align__(16) unsigned char sAh[128 * ROWB];
    __shared__ __align__(16) unsigned char sAl[128 * ROWB];
    __shared__ __align__(16) unsigned char sBh[128 * ROWB];
    __shared__ __align__(16) unsigned char sBl[128 * ROWB];

    const uint32_t uAh = smem_u32(sAh);
    const uint32_t uAl = smem_u32(sAl);
    const uint32_t uBh = smem_u32(sBh);
    const uint32_t uBl = smem_u32(sBl);

    const int tid  = threadIdx.x;
    const int wid  = tid >> 5;
    const int lane = tid & 31;
    const int wm   = wid & 3;    // 4 warps over M (32 rows each)
    const int wn   = wid >> 2;   // 2 warps over N (64 cols each)
    const int m0   = blockIdx.x * 128;

    float acc[2][8][4];
#pragma unroll
    for (int i = 0; i < 2; i++)
#pragma unroll
        for (int j = 0; j < 8; j++)
#pragma unroll
            for (int k = 0; k < 4; k++) acc[i][j][k] = 0.f;

    for (int c = 0; c < 12; c++) {
        __syncthreads();
        // ---- B chunk hi/lo via cp.async (no register round-trip) ----
        {
            const unsigned char* gh = g_Bhi + c * 8192;
            const unsigned char* gl = g_Blo + c * 8192;
#pragma unroll
            for (int j = 0; j < 2; j++) {
                int i = tid + j * 256;          // 0..511 16B-chunks
                int r = i >> 2, g = i & 3;
                CP_ASYNC16(uBh + r * ROWB + g * 16, gh + r * 64 + g * 16);
                CP_ASYNC16(uBl + r * ROWB + g * 16, gl + r * 64 + g * 16);
            }
            CP_COMMIT();
        }
        // ---- load + split A chunk ----
        {
            const int k0 = (c & 3) * 32;
            const float* Ab = (c < 4) ? g_Y : (c < 8 ? g_Y + (size_t)V * DD : x);
            const bool is_loop = (c >= 8);
#pragma unroll
            for (int j = 0; j < 4; j++) {
                int i = tid + j * 256;
                int r = i >> 3, g = i & 7;
                int v = m0 + r;
                float4 z = make_float4(0.f, 0.f, 0.f, 0.f);
                if (v < V)
                    z = *reinterpret_cast<const float4*>(Ab + (size_t)v * DD + k0 + g * 4);
                if (is_loop) {
                    float4 lr = __ldg(reinterpret_cast<const float4*>(loop_rel + k0 + g * 4));
                    z.x *= lr.x; z.y *= lr.y; z.z *= lr.z; z.w *= lr.w;
                }
                uint2 hi, lo;
                split4(z, hi, lo);
                *reinterpret_cast<uint2*>(sAh + r * ROWB + g * 8) = hi;
                *reinterpret_cast<uint2*>(sAl + r * ROWB + g * 8) = lo;
            }
        }
        CP_WAIT0();
        __syncthreads();

        // ---- mma over 2 K16 steps; pass order hh, lh, hl keeps regs low ----
#pragma unroll
        for (int k16 = 0; k16 < 2; k16++) {
            const uint32_t kb = k16 * 32 + ((lane >> 4) << 4);
            const uint32_t arow = (uint32_t)(wm * 32 + (lane & 15)) * ROWB + kb;
            const uint32_t brow = (uint32_t)(wn * 64 + (lane & 15)) * ROWB + kb;

            uint32_t ah[2][4], al[2][4], bb[4][4];
            // pass 1: Ahi * Bhi
#pragma unroll
            for (int mt = 0; mt < 2; mt++) LDSM4(ah[mt], uAh + arow + mt * 16 * ROWB);
#pragma unroll
            for (int nb = 0; nb < 4; nb++) LDSM4(bb[nb], uBh + brow + nb * 16 * ROWB);
#pragma unroll
            for (int mt = 0; mt < 2; mt++)
#pragma unroll
                for (int nb = 0; nb < 4; nb++) {
                    MMA16816(acc[mt][nb * 2 + 0], ah[mt], bb[nb][0], bb[nb][2]);
                    MMA16816(acc[mt][nb * 2 + 1], ah[mt], bb[nb][1], bb[nb][3]);
                }
            // pass 2: Alo * Bhi  (bb still holds Bhi; dead afterwards)
#pragma unroll
            for (int mt = 0; mt < 2; mt++) LDSM4(al[mt], uAl + arow + mt * 16 * ROWB);
#pragma unroll
            for (int mt = 0; mt < 2; mt++)
#pragma unroll
                for (int nb = 0; nb < 4; nb++) {
                    MMA16816(acc[mt][nb * 2 + 0], al[mt], bb[nb][0], bb[nb][2]);
                    MMA16816(acc[mt][nb * 2 + 1], al[mt], bb[nb][1], bb[nb][3]);
                }
            // pass 3: Ahi * Blo  (reuse bb registers for Blo)
#pragma unroll
            for (int nb = 0; nb < 4; nb++) LDSM4(bb[nb], uBl + brow + nb * 16 * ROWB);
#pragma unroll
            for (int mt = 0; mt < 2; mt++)
#pragma unroll
                for (int nb = 0; nb < 4; nb++) {
                    MMA16816(acc[mt][nb * 2 + 0], ah[mt], bb[nb][0], bb[nb][2]);
                    MMA16816(acc[mt][nb * 2 + 1], ah[mt], bb[nb][1], bb[nb][3]);
                }
        }
    }

    // ---- epilogue: /3 + bias, store h, accumulate BN stats ----
    const float third = 1.f / 3.f;
    float ssum[16], ssq[16];
#pragma unroll
    for (int i = 0; i < 16; i++) { ssum[i] = 0.f; ssq[i] = 0.f; }

#pragma unroll
    for (int mt = 0; mt < 2; mt++) {
        int rowa = m0 + wm * 32 + mt * 16 + (lane >> 2);
        int rowb = rowa + 8;
#pragma unroll
        for (int nt = 0; nt < 8; nt++) {
            int col = wn * 64 + nt * 8 + (lane & 3) * 2;
            float2 bv = *reinterpret_cast<const float2*>(bias + col);
            float h0 = acc[mt][nt][0] * third + bv.x;
            float h1 = acc[mt][nt][1] * third + bv.y;
            float h2 = acc[mt][nt][2] * third + bv.x;
            float h3 = acc[mt][nt][3] * third + bv.y;
            if (rowa < V) {
                *reinterpret_cast<float2*>(hout + (size_t)rowa * DD + col) =
                    make_float2(h0, h1);
                ssum[nt * 2 + 0] += h0; ssq[nt * 2 + 0] += h0 * h0;
                ssum[nt * 2 + 1] += h1; ssq[nt * 2 + 1] += h1 * h1;
            }
            if (rowb < V) {
                *reinterpret_cast<float2*>(hout + (size_t)rowb * DD + col) =
                    make_float2(h2, h3);
                ssum[nt * 2 + 0] += h2; ssq[nt * 2 + 0] += h2 * h2;
                ssum[nt * 2 + 1] += h3; ssq[nt * 2 + 1] += h3 * h3;
            }
        }
    }
    // reduce over lane bits 2..4 (rows within warp)
#pragma unroll
    for (int i = 0; i < 16; i++) {
#pragma unroll
        for (int off = 4; off <= 16; off <<= 1) {
            ssum[i] += __shfl_xor_sync(0xFFFFFFFFu, ssum[i], off);
            ssq[i]  += __shfl_xor_sync(0xFFFFFFFFu, ssq[i],  off);
        }
    }
    __syncthreads();  // smem reuse
    float* Ssum = reinterpret_cast<float*>(sAh);   // [8][128]
    float* Ssq  = reinterpret_cast<float*>(sAl);   // [8][128]
#pragma unroll
    for (int j = 0; j < 4; j++) { Ssum[tid + j * 256] = 0.f; Ssq[tid + j * 256] = 0.f; }
    __syncthreads();
    if (lane < 4) {
#pragma unroll
        for (int nt = 0; nt < 8; nt++) {
            int col = wn * 64 + nt * 8 + lane * 2;
            Ssum[wid * 128 + col]     = ssum[nt * 2 + 0];
            Ssum[wid * 128 + col + 1] = ssum[nt * 2 + 1];
            Ssq [wid * 128 + col]     = ssq[nt * 2 + 0];
            Ssq [wid * 128 + col + 1] = ssq[nt * 2 + 1];
        }
    }
    __syncthreads();
    if (tid < 128) {
        float a = 0.f, b = 0.f;
#pragma unroll
        for (int w = 0; w < 8; w++) { a += Ssum[w * 128 + tid]; b += Ssq[w * 128 + tid]; }
        atomicAdd(&g_stats[tid],       a);
        atomicAdd(&g_stats[128 + tid], b);
    }
}

// ---------------------------------------------------------------------------
// Kernel 3: BatchNorm + ReLU, in place on h
// ---------------------------------------------------------------------------
__global__ void bn_kernel(float* __restrict__ h, int V) {
    __shared__ float ms[128];
    __shared__ float rs[128];
    if (threadIdx.x < 128) {
        float invn = 1.f / (float)V;
        float s  = g_stats[threadIdx.x];
        float sq = g_stats[128 + threadIdx.x];
        float m  = s * invn;
        float var = sq * invn - m * m;
        ms[threadIdx.x] = m;
        rs[threadIdx.x] = rsqrtf(var + 1e-5f);
    }
    __syncthreads();
    size_t total = (size_t)V * 32;
    float4* h4 = reinterpret_cast<float4*>(h);
    for (size_t i = (size_t)blockIdx.x * blockDim.x + threadIdx.x; i < total;
         i += (size_t)gridDim.x * blockDim.x) {
        int c4 = (int)(i & 31) * 4;
        float4 hv = h4[i];
        hv.x = fmaxf((hv.x - ms[c4 + 0]) * rs[c4 + 0], 0.f);
        hv.y = fmaxf((hv.y - ms[c4 + 1]) * rs[c4 + 1], 0.f);
        hv.z = fmaxf((hv.z - ms[c4 + 2]) * rs[c4 + 2], 0.f);
        hv.w = fmaxf((hv.w - ms[c4 + 3]) * rs[c4 + 3], 0.f);
        h4[i] = hv;
    }
}

// ---------------------------------------------------------------------------
// Kernel 4: rel_repr @ w_rel, 4 rel rows per block
// ---------------------------------------------------------------------------
__global__ void relw_kernel(const float* __restrict__ rel,
                            const float* __restrict__ w_rel,
                            float* __restrict__ out, int R) {
    __shared__ float rr[4][128];
    int r0 = blockIdx.x * 4;
    int c = threadIdx.x;
#pragma unroll
    for (int j = 0; j < 4; j++)
        rr[j][c] = (r0 + j < R) ? rel[(size_t)(r0 + j) * DD + c] : 0.f;
    __syncthreads();
    float a0 = 0.f, a1 = 0.f, a2 = 0.f, a3 = 0.f;
#pragma unroll 4
    for (int k = 0; k < 128; k++) {
        float w = __ldg(&w_rel[(size_t)k * DD + c]);
        a0 += rr[0][k] * w;
        a1 += rr[1][k] * w;
        a2 += rr[2][k] * w;
        a3 += rr[3][k] * w;
    }
    if (r0 + 0 < R) out[(size_t)(r0 + 0) * DD + c] = a0;
    if (r0 + 1 < R) out[(size_t)(r0 + 1) * DD + c] = a1;
    if (r0 + 2 < R) out[(size_t)(r0 + 2) * DD + c] = a2;
    if (r0 + 3 < R) out[(size_t)(r0 + 3) * DD + c] = a3;
}

// ---------------------------------------------------------------------------
extern "C" void kernel_launch(void* const* d_in, const int* in_sizes, int n_in,
                              void* d_out, int out_size) {
    const float* x        = (const float*)d_in[0];
    const float* rel      = (const float*)d_in[1];
    const float* enorm    = (const float*)d_in[2];
    const float* in_w     = (const float*)d_in[3];
    const float* out_w    = (const float*)d_in[4];
    const float* loop_w   = (const float*)d_in[5];
    const float* w_rel    = (const float*)d_in[6];
    const float* loop_rel = (const float*)d_in[7];
    const float* bias     = (const float*)d_in[8];
    const int*   src      = (const int*)d_in[9];
    const int*   dst      = (const int*)d_in[10];
    const int*   et       = (const int*)d_in[11];

    int V = in_sizes[0] / DD;
    int R = in_sizes[1] / DD;
    int E = in_sizes[2];
    int half = E / 2;

    float* h    = (float*)d_out;
    float* out2 = h + (size_t)V * DD;

    void* yptr = nullptr; void* sptr = nullptr;
    cudaGetSymbolAddress(&yptr, g_Y);
    cudaGetSymbolAddress(&sptr, g_stats);
    float* Yin  = (float*)yptr;
    float* Yout = Yin + (size_t)V * DD;
    cudaMemsetAsync(yptr, 0, (size_t)2 * V * DD * sizeof(float), 0);
    cudaMemsetAsync(sptr, 0, 2 * DD * sizeof(float), 0);

    prep_w<<<12, 256>>>(in_w, out_w, loop_w);
    // two passes: per-launch working set (x + half of Y) fits in L2
    edge_kernel<<<(half + 7) / 8, 256>>>(x, rel, enorm, src, dst, et, half, Yin);
    edge_kernel<<<(E - half + 7) / 8, 256>>>(x, rel, enorm + half, src + half,
                                             dst + half, et + half, E - half, Yout);
    gemm_mma<<<(V + 127) / 128, 256>>>(x, loop_rel, bias, h, V);
    bn_kernel<<<1024, 256>>>(h, V);
    relw_kernel<<<(R + 3) / 4, 128>>>(rel, w_rel, out2, R);
}